// round 13
// baseline (speedup 1.0000x reference)
#include <cuda_runtime.h>
#include <cuda_bf16.h>
#include <math.h>
#include <stdint.h>

#define B_  128
#define D_  512
#define H_  512
#define T_  500
#define NG_ 1536   // 3*H : [r|z|h]
#define NCTA 128

// ---------------- static device scratch ----------------
__device__ float g_Wpack[D_ * NG_];
__device__ float g_bpack[NG_];
__device__ float g_Acat[H_ * NG_];               // [k=512][g=1536] fp32
__device__ float g_ccat[NG_];
__device__ float g_ccatP[NG_];                   // permuted per-CTA-strip bias
__device__ float g_h[B_ * H_];                   // init only (loop keeps h in regs)
__device__ float g_Gz[B_ * H_];                  // init only
__device__ float g_Gh[B_ * H_];                  // init only
__device__ __nv_bfloat16 g_Ath[NG_ * H_];        // permuted Acat^T hi [strip rows][k]
__device__ __nv_bfloat16 g_Atl[NG_ * H_];
__device__ __nv_bfloat16 g_Uth[H_ * H_];         // Uh^T hi [n][k]
__device__ __nv_bfloat16 g_Utl[H_ * H_];
__device__ __nv_bfloat16 g_Woth[H_ * D_];        // Wo^T hi [n][k]
__device__ __nv_bfloat16 g_Wotl[H_ * D_];
__device__ __nv_bfloat16 g_hh[B_ * H_];          // h split (exchange)
__device__ __nv_bfloat16 g_hl[B_ * H_];
__device__ __nv_bfloat16 g_rhh[B_ * H_];         // (r*h) split (exchange)
__device__ __nv_bfloat16 g_rhl[B_ * H_];
__device__ __nv_bfloat16 g_histh[(size_t)(T_ - 1) * B_ * H_];
__device__ __nv_bfloat16 g_histl[(size_t)(T_ - 1) * B_ * H_];

// per-m-group barrier state (4 groups x 32 CTAs), 128B apart
__device__ unsigned g_grpArr[4 * 32];
__device__ unsigned g_grpGen[4 * 32];

__device__ __forceinline__ float sigmoidf_(float x) { return 1.f / (1.f + __expf(-x)); }

__device__ __forceinline__ unsigned atom_add_rel(unsigned* p, unsigned v) {
  unsigned old;
  asm volatile("atom.add.release.gpu.u32 %0, [%1], %2;"
               : "=r"(old) : "l"(p), "r"(v) : "memory");
  return old;
}
__device__ __forceinline__ unsigned ld_acq(const unsigned* p) {
  unsigned v;
  asm volatile("ld.global.acquire.gpu.u32 %0, [%1];" : "=r"(v) : "l"(p) : "memory");
  return v;
}

// group barrier: only the 32 CTAs sharing an m-block synchronize (release/acquire)
__device__ __forceinline__ void gbar(int grp) {
  __syncthreads();
  if (threadIdx.x == 0) {
    unsigned* arr = &g_grpArr[grp * 32];
    unsigned* gen = &g_grpGen[grp * 32];
    unsigned gv = *(volatile unsigned*)gen;
    if (atom_add_rel(arr, 1u) == 31u) {
      *(volatile unsigned*)arr = 0u;
      asm volatile("st.global.release.gpu.u32 [%0], %1;"
                   :: "l"(gen), "r"(gv + 1u) : "memory");
    } else {
      while (ld_acq(gen) == gv) {}
    }
  }
  __syncthreads();
}

// ---------------- mma.sync / ldmatrix / cp.async primitives ----------------
__device__ __forceinline__ uint32_t smem_u32(const void* p) {
  uint32_t a;
  asm("{ .reg .u64 t; cvta.to.shared.u64 t, %1; cvt.u32.u64 %0, t; }" : "=r"(a) : "l"(p));
  return a;
}
__device__ __forceinline__ void cp16(uint32_t dst, const void* src) {
  asm volatile("cp.async.cg.shared.global [%0], [%1], 16;" :: "r"(dst), "l"(src));
}
#define CP_COMMIT() asm volatile("cp.async.commit_group;" ::: "memory")
#define CP_WAIT(n)  asm volatile("cp.async.wait_group %0;" :: "n"(n) : "memory")
__device__ __forceinline__ void lsm4(uint32_t* r, uint32_t a) {
  asm volatile("ldmatrix.sync.aligned.m8n8.x4.shared.b16 {%0,%1,%2,%3}, [%4];"
               : "=r"(r[0]), "=r"(r[1]), "=r"(r[2]), "=r"(r[3]) : "r"(a));
}
__device__ __forceinline__ void mma_bf16(float* d, const uint32_t* a, const uint32_t* b) {
  asm volatile(
      "mma.sync.aligned.m16n8k16.row.col.f32.bf16.bf16.f32 "
      "{%0,%1,%2,%3}, {%4,%5,%6,%7}, {%8,%9}, {%0,%1,%2,%3};"
      : "+f"(d[0]), "+f"(d[1]), "+f"(d[2]), "+f"(d[3])
      : "r"(a[0]), "r"(a[1]), "r"(a[2]), "r"(a[3]), "r"(b[0]), "r"(b[1]));
}
__device__ __forceinline__ uint32_t swz(int r, int c) {
  return (uint32_t)(r * 1024 + (((c) ^ (r & 7)) << 4));
}
__device__ __forceinline__ uint32_t swz128(int r, int c) {
  return (uint32_t)(r * 128 + ((c ^ (r & 7)) << 4));
}

// smem offsets for recur kernel (dynamic, 212 KB)
#define WA_HI  0u
#define WA_LO  49152u
#define WB_HI  98304u
#define WB_LO  114688u
#define ACT_HI 131072u
#define ACT_LO 163840u
#define SCR_   196608u
#define RSMEM  217088

// ---------------- persistent recurrence kernel: 128 CTAs x 256 thr ----------------
// Warps: wm=(w&1)*16 (m half), wk=w>>1 (K quarter, k128 each).
// Stage A: warp tile m16 x n48 (strip rows [z0 gh0 r0 | z1 gh1 r1]); stage B: m16 x n16.
// 4-way K reduction to wk=0 warps, whose threads own the same (m,u) in both stages;
// z, gh-preact, h stay in registers across stages and steps.
__global__ void __launch_bounds__(256)
recur_kernel() {
  extern __shared__ char smem[];
  const uint32_t sb = smem_u32(smem);
  float* scr = (float*)(smem + SCR_);
  const int tid = threadIdx.x, bid = blockIdx.x;
  const int w = tid >> 5, lid = tid & 31;
  const int g = lid >> 2, tig = lid & 3;
  const int wm = (w & 1) * 16;
  const int wk = w >> 1;
  const int grp = bid & 3;
  const int m0 = grp * 32;
  const int strip = bid >> 2;           // [0,32)
  const int n0A = strip * 48;
  const int n0B = strip * 16;
  const int rA = wm + (lid & 15);
  const int rB16 = (lid & 7) + ((lid >> 4) << 3);
  const int cA = lid >> 4;
  const int cSel = (lid >> 3) & 1;
  const int m1 = m0 + wm + g, m2 = m1 + 8;
  // warp-private act load indices: rows [wm, wm+16), cols [wk*128, wk*128+128)
  const int ldRow = wm + (lid >> 1);
  const int ldC0 = wk * 16 + (lid & 1) * 8;

  // ---- one-time: load weight strips into smem ----
  #pragma unroll
  for (int i = 0; i < 12; i++) {
    int idx = tid + i * 256, r = idx >> 6, c = idx & 63;
    size_t go = (size_t)(n0A + r) * 512 + c * 8;
    cp16(sb + WA_HI + swz(r, c), &g_Ath[go]);
    cp16(sb + WA_LO + swz(r, c), &g_Atl[go]);
  }
  #pragma unroll
  for (int i = 0; i < 4; i++) {
    int idx = tid + i * 256, r = idx >> 6, c = idx & 63;
    size_t go = (size_t)(n0B + r) * 512 + c * 8;
    cp16(sb + WB_HI + swz(r, c), &g_Uth[go]);
    cp16(sb + WB_LO + swz(r, c), &g_Utl[go]);
  }
  CP_COMMIT();
  CP_WAIT(0);
  __syncthreads();

  // persistent per-thread state + hoisted biases (wk==0 warps: w<2)
  float zk[8], ghk[8], hkv[8];
  float2 ccz0, ccg0, ccr0, ccz1, ccg1, ccr1;
  if (w < 2) {
    #pragma unroll
    for (int cg = 0; cg < 2; cg++) {
      int un = n0B + cg * 8 + tig * 2;
      float2 a = *(const float2*)&g_h[m1 * 512 + un];
      float2 b = *(const float2*)&g_h[m2 * 512 + un];
      hkv[cg * 4 + 0] = a.x; hkv[cg * 4 + 1] = a.y;
      hkv[cg * 4 + 2] = b.x; hkv[cg * 4 + 3] = b.y;
    }
    ccz0 = *(const float2*)&g_ccatP[n0A + 0 + tig * 2];
    ccg0 = *(const float2*)&g_ccatP[n0A + 8 + tig * 2];
    ccr0 = *(const float2*)&g_ccatP[n0A + 16 + tig * 2];
    ccz1 = *(const float2*)&g_ccatP[n0A + 24 + tig * 2];
    ccg1 = *(const float2*)&g_ccatP[n0A + 32 + tig * 2];
    ccr1 = *(const float2*)&g_ccatP[n0A + 40 + tig * 2];
  }

  for (int t = 2; t < T_; t++) {
    // ================= Stage A =================
    {
      // warp-private act load (own m16 x k128 region) — no CTA sync needed
      #pragma unroll
      for (int j = 0; j < 8; j++) {
        int ch = ldC0 + j;
        int go = (m0 + ldRow) * 512 + ch * 8;
        cp16(sb + ACT_HI + swz(ldRow, ch), &g_hh[go]);
        cp16(sb + ACT_LO + swz(ldRow, ch), &g_hl[go]);
      }
      CP_COMMIT();
      CP_WAIT(0);
      __syncwarp();
      float aZ0[4] = {}, aG0[4] = {}, aR0[4] = {};
      float aZ1[4] = {}, aG1[4] = {}, aR1[4] = {};
      #pragma unroll
      for (int s = 0; s < 8; s++) {
        int ks = wk * 8 + s;
        uint32_t Ah[4], Al[4], B0h[4], B1h[4], B2h[4], B0l[4], B1l[4], B2l[4];
        uint32_t ao = swz(rA, ks * 2 + cA);
        lsm4(Ah, sb + ACT_HI + ao);
        lsm4(Al, sb + ACT_LO + ao);
        int c = ks * 2 + cSel;
        lsm4(B0h, sb + WA_HI + swz(rB16, c));
        lsm4(B1h, sb + WA_HI + swz(16 + rB16, c));
        lsm4(B2h, sb + WA_HI + swz(32 + rB16, c));
        lsm4(B0l, sb + WA_LO + swz(rB16, c));
        lsm4(B1l, sb + WA_LO + swz(16 + rB16, c));
        lsm4(B2l, sb + WA_LO + swz(32 + rB16, c));
        // B0: regs01=z0 regs23=gh0 ; B1: 01=r0 23=z1 ; B2: 01=gh1 23=r1
        mma_bf16(aZ0, Ah, B0h);     mma_bf16(aZ0, Ah, B0l);     mma_bf16(aZ0, Al, B0h);
        mma_bf16(aG0, Ah, B0h + 2); mma_bf16(aG0, Ah, B0l + 2); mma_bf16(aG0, Al, B0h + 2);
        mma_bf16(aR0, Ah, B1h);     mma_bf16(aR0, Ah, B1l);     mma_bf16(aR0, Al, B1h);
        mma_bf16(aZ1, Ah, B1h + 2); mma_bf16(aZ1, Ah, B1l + 2); mma_bf16(aZ1, Al, B1h + 2);
        mma_bf16(aG1, Ah, B2h);     mma_bf16(aG1, Ah, B2l);     mma_bf16(aG1, Al, B2h);
        mma_bf16(aR1, Ah, B2h + 2); mma_bf16(aR1, Ah, B2l + 2); mma_bf16(aR1, Al, B2h + 2);
      }
      // 4-way K reduction to wk=0 warps
      if (w >= 2) {
        float* p = scr + (size_t)(((wk - 1) * 2 + (w & 1)) * 32 + lid) * 25;
        #pragma unroll
        for (int e = 0; e < 4; e++) { p[e] = aZ0[e]; p[4 + e] = aG0[e]; p[8 + e] = aR0[e]; }
        #pragma unroll
        for (int e = 0; e < 4; e++) { p[12 + e] = aZ1[e]; p[16 + e] = aG1[e]; p[20 + e] = aR1[e]; }
      }
      __syncthreads();
      if (w < 2) {
        #pragma unroll
        for (int q = 0; q < 3; q++) {
          float* p = scr + (size_t)((q * 2 + w) * 32 + lid) * 25;
          #pragma unroll
          for (int e = 0; e < 4; e++) { aZ0[e] += p[e]; aG0[e] += p[4 + e]; aR0[e] += p[8 + e]; }
          #pragma unroll
          for (int e = 0; e < 4; e++) { aZ1[e] += p[12 + e]; aG1[e] += p[16 + e]; aR1[e] += p[20 + e]; }
        }
        // epilogue: z, gh -> regs ; rh -> split + exchange
        zk[0] = sigmoidf_(aZ0[0] + ccz0.x); zk[1] = sigmoidf_(aZ0[1] + ccz0.y);
        zk[2] = sigmoidf_(aZ0[2] + ccz0.x); zk[3] = sigmoidf_(aZ0[3] + ccz0.y);
        zk[4] = sigmoidf_(aZ1[0] + ccz1.x); zk[5] = sigmoidf_(aZ1[1] + ccz1.y);
        zk[6] = sigmoidf_(aZ1[2] + ccz1.x); zk[7] = sigmoidf_(aZ1[3] + ccz1.y);
        ghk[0] = aG0[0] + ccg0.x; ghk[1] = aG0[1] + ccg0.y;
        ghk[2] = aG0[2] + ccg0.x; ghk[3] = aG0[3] + ccg0.y;
        ghk[4] = aG1[0] + ccg1.x; ghk[5] = aG1[1] + ccg1.y;
        ghk[6] = aG1[2] + ccg1.x; ghk[7] = aG1[3] + ccg1.y;
        float rh[8];
        rh[0] = sigmoidf_(aR0[0] + ccr0.x) * hkv[0];
        rh[1] = sigmoidf_(aR0[1] + ccr0.y) * hkv[1];
        rh[2] = sigmoidf_(aR0[2] + ccr0.x) * hkv[2];
        rh[3] = sigmoidf_(aR0[3] + ccr0.y) * hkv[3];
        rh[4] = sigmoidf_(aR1[0] + ccr1.x) * hkv[4];
        rh[5] = sigmoidf_(aR1[1] + ccr1.y) * hkv[5];
        rh[6] = sigmoidf_(aR1[2] + ccr1.x) * hkv[6];
        rh[7] = sigmoidf_(aR1[3] + ccr1.y) * hkv[7];
        #pragma unroll
        for (int cg = 0; cg < 2; cg++) {
          int un = n0B + cg * 8 + tig * 2;
          __nv_bfloat162 ph2, pl2;
          ph2.x = __float2bfloat16(rh[cg * 4 + 0]); ph2.y = __float2bfloat16(rh[cg * 4 + 1]);
          pl2.x = __float2bfloat16(rh[cg * 4 + 0] - __bfloat162float(ph2.x));
          pl2.y = __float2bfloat16(rh[cg * 4 + 1] - __bfloat162float(ph2.y));
          *(__nv_bfloat162*)&g_rhh[m1 * 512 + un] = ph2;
          *(__nv_bfloat162*)&g_rhl[m1 * 512 + un] = pl2;
          ph2.x = __float2bfloat16(rh[cg * 4 + 2]); ph2.y = __float2bfloat16(rh[cg * 4 + 3]);
          pl2.x = __float2bfloat16(rh[cg * 4 + 2] - __bfloat162float(ph2.x));
          pl2.y = __float2bfloat16(rh[cg * 4 + 3] - __bfloat162float(ph2.y));
          *(__nv_bfloat162*)&g_rhh[m2 * 512 + un] = ph2;
          *(__nv_bfloat162*)&g_rhl[m2 * 512 + un] = pl2;
        }
      }
    }
    gbar(grp);

    // ================= Stage B =================
    {
      #pragma unroll
      for (int j = 0; j < 8; j++) {
        int ch = ldC0 + j;
        int go = (m0 + ldRow) * 512 + ch * 8;
        cp16(sb + ACT_HI + swz(ldRow, ch), &g_rhh[go]);
        cp16(sb + ACT_LO + swz(ldRow, ch), &g_rhl[go]);
      }
      CP_COMMIT();
      CP_WAIT(0);
      __syncwarp();
      float aQ0[4] = {}, aQ1[4] = {};
      #pragma unroll
      for (int s = 0; s < 8; s++) {
        int ks = wk * 8 + s;
        uint32_t Ah[4], Al[4], Bh[4], Bl[4];
        uint32_t ao = swz(rA, ks * 2 + cA);
        lsm4(Ah, sb + ACT_HI + ao);
        lsm4(Al, sb + ACT_LO + ao);
        int c = ks * 2 + cSel;
        lsm4(Bh, sb + WB_HI + swz(rB16, c));
        lsm4(Bl, sb + WB_LO + swz(rB16, c));
        mma_bf16(aQ0, Ah, Bh);     mma_bf16(aQ0, Ah, Bl);     mma_bf16(aQ0, Al, Bh);
        mma_bf16(aQ1, Ah, Bh + 2); mma_bf16(aQ1, Ah, Bl + 2); mma_bf16(aQ1, Al, Bh + 2);
      }
      if (w >= 2) {
        float* p = scr + (size_t)(((wk - 1) * 2 + (w & 1)) * 32 + lid) * 9;
        #pragma unroll
        for (int e = 0; e < 4; e++) { p[e] = aQ0[e]; p[4 + e] = aQ1[e]; }
      }
      __syncthreads();
      if (w < 2) {
        #pragma unroll
        for (int q = 0; q < 3; q++) {
          float* p = scr + (size_t)((q * 2 + w) * 32 + lid) * 9;
          #pragma unroll
          for (int e = 0; e < 4; e++) { aQ0[e] += p[e]; aQ1[e] += p[4 + e]; }
        }
        size_t hb = (size_t)(t - 1) * (B_ * H_);
        #pragma unroll
        for (int cg = 0; cg < 2; cg++) {
          float* aQ = cg ? aQ1 : aQ0;
          float hn[4];
          #pragma unroll
          for (int e = 0; e < 4; e++) {
            float h0 = hkv[cg * 4 + e];
            float hp = tanhf(ghk[cg * 4 + e] + aQ[e]);
            hn[e] = fminf(fmaxf(fmaf(zk[cg * 4 + e], hp - h0, h0), -5.f), 5.f);
            hkv[cg * 4 + e] = hn[e];
          }
          int un = n0B + cg * 8 + tig * 2;
          __nv_bfloat162 ph2, pl2;
          ph2.x = __float2bfloat16(hn[0]); ph2.y = __float2bfloat16(hn[1]);
          pl2.x = __float2bfloat16(hn[0] - __bfloat162float(ph2.x));
          pl2.y = __float2bfloat16(hn[1] - __bfloat162float(ph2.y));
          *(__nv_bfloat162*)&g_hh[m1 * 512 + un] = ph2;
          *(__nv_bfloat162*)&g_hl[m1 * 512 + un] = pl2;
          *(__nv_bfloat162*)&g_histh[hb + m1 * 512 + un] = ph2;
          *(__nv_bfloat162*)&g_histl[hb + m1 * 512 + un] = pl2;
          ph2.x = __float2bfloat16(hn[2]); ph2.y = __float2bfloat16(hn[3]);
          pl2.x = __float2bfloat16(hn[2] - __bfloat162float(ph2.x));
          pl2.y = __float2bfloat16(hn[3] - __bfloat162float(ph2.y));
          *(__nv_bfloat162*)&g_hh[m2 * 512 + un] = ph2;
          *(__nv_bfloat162*)&g_hl[m2 * 512 + un] = pl2;
          *(__nv_bfloat162*)&g_histh[hb + m2 * 512 + un] = ph2;
          *(__nv_bfloat162*)&g_histl[hb + m2 * 512 + un] = pl2;
        }
      }
    }
    gbar(grp);
  }
}

// ---------------- final projection: out[:,1..,:] = hist @ Wo + bo (bf16x3 MMA) ----------------
__global__ void __launch_bounds__(256)
proj_kernel(float* __restrict__ out, const float* __restrict__ bo) {
  extern __shared__ char dsm[];
  const uint32_t sb = smem_u32(dsm);
  const int tid = threadIdx.x, w = tid >> 5, lid = tid & 31;
  const int g = lid >> 2, tig = lid & 3;
  const int by = blockIdx.y;
  const int n0 = blockIdx.x * 128;
  const int wm = (w & 3) * 32;
  const int wn = (w >> 2) * 64;
  const size_t mbase = (size_t)by * 128;
  float acc[2][8][4] = {};

  #pragma unroll 1
  for (int kc = 0; kc < 8; kc++) {
    if (kc == 0) {
      #pragma unroll
      for (int i = 0; i < 4; i++) {
        int idx = tid + i * 256, r = idx >> 3, c = idx & 7;
        uint32_t sw = swz128(r, c);
        size_t eA = (mbase + r) * 512 + c * 8;
        int eB = (n0 + r) * 512 + c * 8;
        cp16(sb + sw, &g_histh[eA]);
        cp16(sb + 16384 + sw, &g_histl[eA]);
        cp16(sb + 32768 + sw, &g_Woth[eB]);
        cp16(sb + 49152 + sw, &g_Wotl[eB]);
      }
      CP_COMMIT();
    }
    if (kc < 7) {
      uint32_t base = sb + ((kc + 1) & 1) * 65536;
      int ko = (kc + 1) * 64;
      #pragma unroll
      for (int i = 0; i < 4; i++) {
        int idx = tid + i * 256, r = idx >> 3, c = idx & 7;
        uint32_t sw = swz128(r, c);
        size_t eA = (mbase + r) * 512 + ko + c * 8;
        int eB = (n0 + r) * 512 + ko + c * 8;
        cp16(base + sw, &g_histh[eA]);
        cp16(base + 16384 + sw, &g_histl[eA]);
        cp16(base + 32768 + sw, &g_Woth[eB]);
        cp16(base + 49152 + sw, &g_Wotl[eB]);
      }
      CP_COMMIT();
      CP_WAIT(1);
    } else {
      CP_WAIT(0);
    }
    __syncthreads();
    uint32_t base = sb + (kc & 1) * 65536;
    #pragma unroll
    for (int s = 0; s < 4; s++) {
      int cA = 2 * s + (lid >> 4);
      int cB = 2 * s + ((lid >> 3) & 1);
      uint32_t Ah[2][4], Al[2][4];
      #pragma unroll
      for (int mt = 0; mt < 2; mt++) {
        int rA = wm + mt * 16 + (lid & 15);
        uint32_t aAddr = base + swz128(rA, cA);
        lsm4(Ah[mt], aAddr);
        lsm4(Al[mt], aAddr + 16384);
      }
      #pragma unroll
      for (int p = 0; p < 4; p++) {
        int rB = wn + p * 16 + (lid & 7) + ((lid >> 4) << 3);
        uint32_t bAddr = base + 32768 + swz128(rB, cB);
        uint32_t Bh[4], Bl[4];
        lsm4(Bh, bAddr);
        lsm4(Bl, bAddr + 16384);
        #pragma unroll
        for (int mt = 0; mt < 2; mt++) {
          mma_bf16(acc[mt][2 * p], Ah[mt], Bh);
          mma_bf16(acc[mt][2 * p], Ah[mt], Bl);
          mma_bf16(acc[mt][2 * p], Al[mt], Bh);
          mma_bf16(acc[mt][2 * p + 1], Ah[mt], Bh + 2);
          mma_bf16(acc[mt][2 * p + 1], Ah[mt], Bl + 2);
          mma_bf16(acc[mt][2 * p + 1], Al[mt], Bh + 2);
        }
      }
    }
    __syncthreads();
  }
  #pragma unroll
  for (int mt = 0; mt < 2; mt++) {
    #pragma unroll
    for (int nt = 0; nt < 8; nt++) {
      int n = n0 + wn + nt * 8 + tig * 2;
      float2 bb = *(const float2*)&bo[n];
      #pragma unroll
      for (int rr = 0; rr < 2; rr++) {
        int b = wm + mt * 16 + g + rr * 8;
        float v0 = acc[mt][nt][rr * 2 + 0] + bb.x;
        float v1 = acc[mt][nt][rr * 2 + 1] + bb.y;
        *(float2*)&out[(size_t)b * ((size_t)T_ * D_) + (size_t)(by + 1) * D_ + n] =
            make_float2(v0, v1);
      }
    }
  }
}

// ---------------- fused setup kernels ----------------
struct EpiFold {
  const float *Ur, *Uz;
  __device__ __forceinline__ void operator()(int m, int n, float v) const {
    if (n < H_)            v += Ur[m * H_ + n];
    else if (n < 2 * H_)   v += Uz[m * H_ + (n - H_)];
    g_Acat[m * NG_ + n] = v;
  }
};
struct EpiStep1 {
  __device__ __forceinline__ void operator()(int m, int n, float v) const {
    v += g_bpack[H_ + n];
    if (n < H_) g_Gz[m * H_ + n] = v;
    else        g_Gh[m * H_ + (n - H_)] = v;
  }
};

template <class Epi>
__device__ __forceinline__ void gemm_body(const float* __restrict__ A,
                                          const float* __restrict__ Bm,
                                          int K, int ldb, Epi epi, int bxi, int byi) {
  constexpr int BM = 32, BK = 32, BN = 64, NTHR = 256;
  __shared__ __align__(16) float As[BK][BM + 1];
  __shared__ __align__(16) float Bs[BK][BN];
  const int tid = threadIdx.x;
  const int bm = byi * BM;
  const int bn = bxi * BN;
  const int tx = tid % (BN / 4);
  const int ty = tid / (BN / 4);
  float acc[2][4] = {};
  for (int k0 = 0; k0 < K; k0 += BK) {
    #pragma unroll
    for (int i = tid * 4; i < BM * BK; i += NTHR * 4) {
      int m = i / BK, k = i % BK;
      float4 v = *(const float4*)(A + (size_t)(bm + m) * K + k0 + k);
      As[k + 0][m] = v.x; As[k + 1][m] = v.y; As[k + 2][m] = v.z; As[k + 3][m] = v.w;
    }
    #pragma unroll
    for (int i = tid * 4; i < BK * BN; i += NTHR * 4) {
      int k = i / BN, n = i % BN;
      *(float4*)&Bs[k][n] = *(const float4*)(Bm + (size_t)(k0 + k) * ldb + bn + n);
    }
    __syncthreads();
    #pragma unroll
    for (int kk = 0; kk < BK; kk++) {
      float a0 = As[kk][ty * 2 + 0];
      float a1 = As[kk][ty * 2 + 1];
      float4 b4 = *(float4*)&Bs[kk][tx * 4];
      acc[0][0] = fmaf(a0, b4.x, acc[0][0]);
      acc[0][1] = fmaf(a0, b4.y, acc[0][1]);
      acc[0][2] = fmaf(a0, b4.z, acc[0][2]);
      acc[0][3] = fmaf(a0, b4.w, acc[0][3]);
      acc[1][0] = fmaf(a1, b4.x, acc[1][0]);
      acc[1][1] = fmaf(a1, b4.y, acc[1][1]);
      acc[1][2] = fmaf(a1, b4.z, acc[1][2]);
      acc[1][3] = fmaf(a1, b4.w, acc[1][3]);
    }
    __syncthreads();
  }
  #pragma unroll
  for (int i = 0; i < 2; i++)
    #pragma unroll
    for (int j = 0; j < 4; j++)
      epi(bm + ty * 2 + i, bn + tx * 4 + j, acc[i][j]);
}

// launch slot 0: pack weights + reset barriers
__global__ void pack_kernel(const float* __restrict__ Wr, const float* __restrict__ Wz,
                            const float* __restrict__ Wh, const float* __restrict__ br,
                            const float* __restrict__ bz, const float* __restrict__ bh) {
  int idx = blockIdx.x * blockDim.x + threadIdx.x;
  if (idx < 4) { g_grpArr[idx * 32] = 0; g_grpGen[idx * 32] = 0; }
  if (idx < NG_) {
    int sel = idx >> 9, jl = idx & 511;
    g_bpack[idx] = (sel == 0) ? br[jl] : (sel == 1) ? bz[jl] : bh[jl];
  }
  if (idx < D_ * NG_) {
    int d = idx / NG_, j = idx % NG_;
    int sel = j >> 9, jl = j & 511;
    const float* W = (sel == 0) ? Wr : (sel == 1) ? Wz : Wh;
    g_Wpack[idx] = W[d * H_ + jl];
  }
}

// launch slot 1: fold-GEMM (384 blk) + step1-GEMM (64 blk) + ccat (192 blk)
__global__ void __launch_bounds__(256)
setup1_kernel(const float* __restrict__ Wo, const float* __restrict__ Ur,
              const float* __restrict__ Uz, const float* __restrict__ inputs,
              const float* __restrict__ bo) {
  int b = blockIdx.x;
  if (b < 384) {
    gemm_body(Wo, g_Wpack, D_, NG_, EpiFold{Ur, Uz}, b % 24, b / 24);
  } else if (b < 448) {
    int bb = b - 384;
    gemm_body(inputs, g_Wpack + H_, D_, NG_, EpiStep1{}, bb % 16, bb / 16);
  } else {
    int w = (b - 448) * 8 + (threadIdx.x >> 5);
    int lane = threadIdx.x & 31;
    if (w < NG_) {
      float acc = 0.f;
      for (int d = lane; d < D_; d += 32)
        acc = fmaf(bo[d], g_Wpack[(size_t)d * NG_ + w], acc);
      #pragma unroll
      for (int o = 16; o; o >>= 1) acc += __shfl_xor_sync(0xffffffffu, acc, o);
      if (lane == 0) g_ccat[w] = acc + g_bpack[w];
    }
  }
}

// launch slot 2: PERMUTED bf16 splits (3072 blk) + combine1 (256 blk)
__global__ void __launch_bounds__(256)
setup2_kernel(const float* __restrict__ Uh, const float* __restrict__ Wo) {
  int b = blockIdx.x;
  if (b < 3072) {
    int idx = b * 256 + threadIdx.x;
    if (idx < NG_ * H_) {
      int row = idx >> 9, k = idx & 511;
      int p = row / 48, c = row % 48;
      int gidx = c / 24, j = c % 24;
      int u = p * 16 + gidx * 8 + (j & 7);
      int gate = j >> 3;                 // 0:z 1:hcand 2:r
      int src = (gate == 0) ? 512 + u : (gate == 1) ? 1024 + u : u;
      float x = g_Acat[(size_t)k * NG_ + src];
      __nv_bfloat16 hi = __float2bfloat16(x);
      g_Ath[idx] = hi;
      g_Atl[idx] = __float2bfloat16(x - __bfloat162float(hi));
      if (k == 0) g_ccatP[row] = g_ccat[src];
    }
    if (idx < H_ * H_) {
      int n = idx >> 9, k = idx & 511;
      float x = Uh[(size_t)k * H_ + n];
      __nv_bfloat16 hi = __float2bfloat16(x);
      g_Uth[idx] = hi;
      g_Utl[idx] = __float2bfloat16(x - __bfloat162float(hi));
      float y = Wo[(size_t)k * D_ + n];
      __nv_bfloat16 hi2 = __float2bfloat16(y);
      g_Woth[idx] = hi2;
      g_Wotl[idx] = __float2bfloat16(y - __bfloat162float(hi2));
    }
  } else {
    int idx = (b - 3072) * 256 + threadIdx.x;
    if (idx < B_ * H_) {
      float z  = sigmoidf_(g_Gz[idx]);
      float hp = tanhf(g_Gh[idx]);
      float hn = fminf(fmaxf(z * hp, -5.f), 5.f);
      g_h[idx] = hn;
      __nv_bfloat16 hi = __float2bfloat16(hn);
      __nv_bfloat16 lo = __float2bfloat16(hn - __bfloat162float(hi));
      g_hh[idx] = hi;
      g_hl[idx] = lo;
      g_histh[idx] = hi;
      g_histl[idx] = lo;
    }
  }
}

__global__ void copy0_kernel(const float* __restrict__ inputs, float* __restrict__ out) {
  int idx = blockIdx.x * blockDim.x + threadIdx.x;
  if (idx >= B_ * D_) return;
  int b = idx / D_, d = idx % D_;
  out[(size_t)b * ((size_t)T_ * D_) + d] = inputs[idx];
}

// ---------------- launch ----------------
extern "C" void kernel_launch(void* const* d_in, const int* in_sizes, int n_in,
                              void* d_out, int out_size) {
  const float* inputs = (const float*)d_in[0];
  const float* Wz = (const float*)d_in[1];
  const float* Wr = (const float*)d_in[2];
  const float* Wh = (const float*)d_in[3];
  const float* Uz = (const float*)d_in[4];
  const float* Ur = (const float*)d_in[5];
  const float* Uh = (const float*)d_in[6];
  const float* bz = (const float*)d_in[7];
  const float* br = (const float*)d_in[8];
  const float* bh = (const float*)d_in[9];
  const float* Wo = (const float*)d_in[10];
  const float* bo = (const float*)d_in[11];
  float* out = (float*)d_out;

  cudaFuncSetAttribute(proj_kernel, cudaFuncAttributeMaxDynamicSharedMemorySize, 131072);
  cudaFuncSetAttribute(recur_kernel, cudaFuncAttributeMaxDynamicSharedMemorySize, RSMEM);

  // slot 0: pack + barrier reset
  pack_kernel<<<(D_ * NG_ + 255) / 256, 256>>>(Wr, Wz, Wh, br, bz, bh);
  // slot 1: fold + ccat + step1 (fused)
  setup1_kernel<<<640, 256>>>(Wo, Ur, Uz, inputs, bo);
  // slot 2: permuted bf16 splits + combine1 (fused)
  setup2_kernel<<<3328, 256>>>(Uh, Wo);
  // slot 3 (ncu-profiled slot): persistent recurrence
  recur_kernel<<<NCTA, 256, RSMEM>>>();
  // slot 4: t=0 output copy
  copy0_kernel<<<(B_ * D_ + 255) / 256, 256>>>(inputs, out);
  // slot 5: deferred projection
  proj_kernel<<<dim3(4, T_ - 1), 256, 131072>>>(out, bo);
}

// round 14
// speedup vs baseline: 1.4557x; 1.4557x over previous
#include <cuda_runtime.h>
#include <cuda_bf16.h>
#include <math.h>
#include <stdint.h>

#define B_  128
#define D_  512
#define H_  512
#define T_  500
#define NG_ 1536   // 3*H : [r|z|h]
#define NCTA 128

// ---------------- static device scratch ----------------
__device__ float g_Wpack[D_ * NG_];
__device__ float g_bpack[NG_];
__device__ float g_Acat[H_ * NG_];               // [k=512][g=1536] fp32
__device__ float g_ccat[NG_];
__device__ float g_ccatP[NG_];                   // permuted per-CTA-strip bias
__device__ float g_h[B_ * H_];                   // init only (loop keeps h in regs)
__device__ float g_Gz[B_ * H_];                  // init only
__device__ float g_Gh[B_ * H_];                  // init only
__device__ __nv_bfloat16 g_Ath[NG_ * H_];        // permuted Acat^T hi [strip rows][k]
__device__ __nv_bfloat16 g_Atl[NG_ * H_];
__device__ __nv_bfloat16 g_Uth[H_ * H_];         // Uh^T hi [n][k]
__device__ __nv_bfloat16 g_Utl[H_ * H_];
__device__ __nv_bfloat16 g_Woth[H_ * D_];        // Wo^T hi [n][k]
__device__ __nv_bfloat16 g_Wotl[H_ * D_];
__device__ __nv_bfloat16 g_hh[B_ * H_];          // h split (exchange)
__device__ __nv_bfloat16 g_hl[B_ * H_];
__device__ __nv_bfloat16 g_rhh[B_ * H_];         // (r*h) split (exchange)
__device__ __nv_bfloat16 g_rhl[B_ * H_];
__device__ __nv_bfloat16 g_histh[(size_t)(T_ - 1) * B_ * H_];
__device__ __nv_bfloat16 g_histl[(size_t)(T_ - 1) * B_ * H_];

// per-m-group barrier state (4 groups x 32 CTAs), 128B apart
__device__ unsigned g_grpArr[4 * 32];
__device__ unsigned g_grpGen[4 * 32];

__device__ __forceinline__ float sigmoidf_(float x) { return 1.f / (1.f + __expf(-x)); }

__device__ __forceinline__ unsigned atom_add_rel(unsigned* p, unsigned v) {
  unsigned old;
  asm volatile("atom.add.release.gpu.u32 %0, [%1], %2;"
               : "=r"(old) : "l"(p), "r"(v) : "memory");
  return old;
}
__device__ __forceinline__ unsigned ld_acq(const unsigned* p) {
  unsigned v;
  asm volatile("ld.global.acquire.gpu.u32 %0, [%1];" : "=r"(v) : "l"(p) : "memory");
  return v;
}

// group barrier: only the 32 CTAs sharing an m-block synchronize (release/acquire)
__device__ __forceinline__ void gbar(int grp) {
  __syncthreads();
  if (threadIdx.x == 0) {
    unsigned* arr = &g_grpArr[grp * 32];
    unsigned* gen = &g_grpGen[grp * 32];
    unsigned gv = *(volatile unsigned*)gen;
    if (atom_add_rel(arr, 1u) == 31u) {
      *(volatile unsigned*)arr = 0u;
      asm volatile("st.global.release.gpu.u32 [%0], %1;"
                   :: "l"(gen), "r"(gv + 1u) : "memory");
    } else {
      while (ld_acq(gen) == gv) {}
    }
  }
  __syncthreads();
}

// ---------------- mma.sync / ldmatrix / cp.async primitives ----------------
__device__ __forceinline__ uint32_t smem_u32(const void* p) {
  uint32_t a;
  asm("{ .reg .u64 t; cvta.to.shared.u64 t, %1; cvt.u32.u64 %0, t; }" : "=r"(a) : "l"(p));
  return a;
}
__device__ __forceinline__ void cp16(uint32_t dst, const void* src) {
  asm volatile("cp.async.cg.shared.global [%0], [%1], 16;" :: "r"(dst), "l"(src));
}
#define CP_COMMIT() asm volatile("cp.async.commit_group;" ::: "memory")
#define CP_WAIT(n)  asm volatile("cp.async.wait_group %0;" :: "n"(n) : "memory")
#define NB_SYNC(id) asm volatile("bar.sync %0, 128;" :: "r"(id) : "memory")
__device__ __forceinline__ void lsm4(uint32_t* r, uint32_t a) {
  asm volatile("ldmatrix.sync.aligned.m8n8.x4.shared.b16 {%0,%1,%2,%3}, [%4];"
               : "=r"(r[0]), "=r"(r[1]), "=r"(r[2]), "=r"(r[3]) : "r"(a));
}
__device__ __forceinline__ void lsm2(uint32_t* r, uint32_t a) {
  asm volatile("ldmatrix.sync.aligned.m8n8.x2.shared.b16 {%0,%1}, [%2];"
               : "=r"(r[0]), "=r"(r[1]) : "r"(a));
}
__device__ __forceinline__ void mma_bf16(float* d, const uint32_t* a, const uint32_t* b) {
  asm volatile(
      "mma.sync.aligned.m16n8k16.row.col.f32.bf16.bf16.f32 "
      "{%0,%1,%2,%3}, {%4,%5,%6,%7}, {%8,%9}, {%0,%1,%2,%3};"
      : "+f"(d[0]), "+f"(d[1]), "+f"(d[2]), "+f"(d[3])
      : "r"(a[0]), "r"(a[1]), "r"(a[2]), "r"(a[3]), "r"(b[0]), "r"(b[1]));
}
__device__ __forceinline__ uint32_t swz(int r, int c) {
  return (uint32_t)(r * 1024 + (((c) ^ (r & 7)) << 4));
}
__device__ __forceinline__ uint32_t swz128(int r, int c) {
  return (uint32_t)(r * 128 + ((c ^ (r & 7)) << 4));
}

// smem offsets for recur kernel (dynamic, 200 KB)
#define WA_HI  0u
#define WA_LO  49152u
#define WB_HI  98304u
#define WB_LO  114688u
#define ACT_HI 131072u
#define ACT_LO 163840u
#define SCR_   196608u
#define RSMEM  204800

// ---------------- persistent recurrence kernel: 128 CTAs x 256 thr ----------------
// R12 structure (measured best): warps wpos(0..3) x wk(0..1); K split in halves;
// CTA-cooperative coalesced act loads; permuted weights; register-resident state.
__global__ void __launch_bounds__(256)
recur_kernel() {
  extern __shared__ char smem[];
  const uint32_t sb = smem_u32(smem);
  float* scr = (float*)(smem + SCR_);
  const int tid = threadIdx.x, bid = blockIdx.x;
  const int w = tid >> 5, lid = tid & 31;
  const int g = lid >> 2, tig = lid & 3;
  const int wpos = w & 3, wk = w >> 2;
  const int grp = bid & 3;
  const int m0 = grp * 32;
  const int strip = bid >> 2;           // [0,32)
  const int n0A = strip * 48;
  const int n0B = strip * 16;
  const int wm = (wpos & 1) * 16;
  const int cg = wpos >> 1;
  const int wnA = cg * 24;
  const int rA = wm + (lid & 15);
  const int rB16 = (lid & 7) + ((lid >> 4) << 3);
  const int rB8 = lid & 7;
  const int cA = lid >> 4;
  const int cSel = (lid >> 3) & 1;
  const int m1 = m0 + wm + g, m2 = m1 + 8;
  const int half = tid >> 7, ltid = tid & 127;
  const int un = n0B + cg * 8 + tig * 2;   // this thread's global unit pair

  // ---- one-time: load weight strips into smem ----
  #pragma unroll
  for (int i = 0; i < 12; i++) {
    int idx = tid + i * 256, r = idx >> 6, c = idx & 63;
    size_t go = (size_t)(n0A + r) * 512 + c * 8;
    cp16(sb + WA_HI + swz(r, c), &g_Ath[go]);
    cp16(sb + WA_LO + swz(r, c), &g_Atl[go]);
  }
  #pragma unroll
  for (int i = 0; i < 4; i++) {
    int idx = tid + i * 256, r = idx >> 6, c = idx & 63;
    size_t go = (size_t)(n0B + r) * 512 + c * 8;
    cp16(sb + WB_HI + swz(r, c), &g_Uth[go]);
    cp16(sb + WB_LO + swz(r, c), &g_Utl[go]);
  }
  CP_COMMIT();
  CP_WAIT(0);
  __syncthreads();

  // persistent per-thread state (warps 0-3)
  float zk[4], ghk[4];
  float2 hk[2] = {make_float2(0.f, 0.f), make_float2(0.f, 0.f)};
  if (w < 4) {
    hk[0] = *(const float2*)&g_h[m1 * 512 + un];
    hk[1] = *(const float2*)&g_h[m2 * 512 + un];
  }

  for (int t = 2; t < T_; t++) {
    // ================= Stage A =================
    {
      #pragma unroll
      for (int kc2 = 0; kc2 < 2; kc2++) {
        int kc = half * 2 + kc2;
        #pragma unroll
        for (int i = 0; i < 4; i++) {
          int idx = ltid + i * 128, r = idx >> 4, cs = idx & 15;
          int go = (m0 + r) * 512 + kc * 128 + cs * 8;
          cp16(sb + ACT_HI + swz(r, kc * 16 + cs), &g_hh[go]);
          cp16(sb + ACT_LO + swz(r, kc * 16 + cs), &g_hl[go]);
        }
        CP_COMMIT();
      }
      float acc0[4] = {}, acc1[4] = {}, acc2[4] = {};
      #pragma unroll
      for (int kc2 = 0; kc2 < 2; kc2++) {
        if (kc2 == 0) CP_WAIT(1); else CP_WAIT(0);
        NB_SYNC(1 + wk);
        #pragma unroll
        for (int s = 0; s < 8; s++) {
          int ks = (wk * 2 + kc2) * 8 + s;
          uint32_t Ah[4], Al[4], Bh[4], Bl[4], Bh2[2], Bl2[2];
          uint32_t ao = swz(rA, ks * 2 + cA);
          lsm4(Ah, sb + ACT_HI + ao);
          lsm4(Al, sb + ACT_LO + ao);
          uint32_t bo = swz(wnA + rB16, ks * 2 + cSel);
          lsm4(Bh, sb + WA_HI + bo);
          lsm4(Bl, sb + WA_LO + bo);
          uint32_t bo2 = swz(wnA + 16 + rB8, ks * 2 + cSel);
          lsm2(Bh2, sb + WA_HI + bo2);
          lsm2(Bl2, sb + WA_LO + bo2);
          mma_bf16(acc0, Ah, Bh);     mma_bf16(acc0, Ah, Bl);     mma_bf16(acc0, Al, Bh);
          mma_bf16(acc1, Ah, Bh + 2); mma_bf16(acc1, Ah, Bl + 2); mma_bf16(acc1, Al, Bh + 2);
          mma_bf16(acc2, Ah, Bh2);    mma_bf16(acc2, Ah, Bl2);    mma_bf16(acc2, Al, Bh2);
        }
      }
      if (w >= 4) {
        int base = (w - 4) * 416 + lid * 13;
        #pragma unroll
        for (int e = 0; e < 4; e++) scr[base + e] = acc0[e];
        #pragma unroll
        for (int e = 0; e < 4; e++) scr[base + 4 + e] = acc1[e];
        #pragma unroll
        for (int e = 0; e < 4; e++) scr[base + 8 + e] = acc2[e];
      }
      __syncthreads();
      if (w < 4) {
        int base = w * 416 + lid * 13;
        #pragma unroll
        for (int e = 0; e < 4; e++) acc0[e] += scr[base + e];
        #pragma unroll
        for (int e = 0; e < 4; e++) acc1[e] += scr[base + 4 + e];
        #pragma unroll
        for (int e = 0; e < 4; e++) acc2[e] += scr[base + 8 + e];
        int rbase = n0A + cg * 24 + tig * 2;
        float2 ccz = *(const float2*)&g_ccatP[rbase + 0];
        float2 cch = *(const float2*)&g_ccatP[rbase + 8];
        float2 ccr = *(const float2*)&g_ccatP[rbase + 16];
        zk[0] = sigmoidf_(acc0[0] + ccz.x); zk[1] = sigmoidf_(acc0[1] + ccz.y);
        zk[2] = sigmoidf_(acc0[2] + ccz.x); zk[3] = sigmoidf_(acc0[3] + ccz.y);
        ghk[0] = acc1[0] + cch.x; ghk[1] = acc1[1] + cch.y;
        ghk[2] = acc1[2] + cch.x; ghk[3] = acc1[3] + cch.y;
        float rh00 = sigmoidf_(acc2[0] + ccr.x) * hk[0].x;
        float rh01 = sigmoidf_(acc2[1] + ccr.y) * hk[0].y;
        float rh10 = sigmoidf_(acc2[2] + ccr.x) * hk[1].x;
        float rh11 = sigmoidf_(acc2[3] + ccr.y) * hk[1].y;
        __nv_bfloat162 ph2, pl2;
        ph2.x = __float2bfloat16(rh00); ph2.y = __float2bfloat16(rh01);
        pl2.x = __float2bfloat16(rh00 - __bfloat162float(ph2.x));
        pl2.y = __float2bfloat16(rh01 - __bfloat162float(ph2.y));
        *(__nv_bfloat162*)&g_rhh[m1 * 512 + un] = ph2;
        *(__nv_bfloat162*)&g_rhl[m1 * 512 + un] = pl2;
        ph2.x = __float2bfloat16(rh10); ph2.y = __float2bfloat16(rh11);
        pl2.x = __float2bfloat16(rh10 - __bfloat162float(ph2.x));
        pl2.y = __float2bfloat16(rh11 - __bfloat162float(ph2.y));
        *(__nv_bfloat162*)&g_rhh[m2 * 512 + un] = ph2;
        *(__nv_bfloat162*)&g_rhl[m2 * 512 + un] = pl2;
      }
    }
    gbar(grp);

    // ================= Stage B =================
    {
      #pragma unroll
      for (int kc2 = 0; kc2 < 2; kc2++) {
        int kc = half * 2 + kc2;
        #pragma unroll
        for (int i = 0; i < 4; i++) {
          int idx = ltid + i * 128, r = idx >> 4, cs = idx & 15;
          int go = (m0 + r) * 512 + kc * 128 + cs * 8;
          cp16(sb + ACT_HI + swz(r, kc * 16 + cs), &g_rhh[go]);
          cp16(sb + ACT_LO + swz(r, kc * 16 + cs), &g_rhl[go]);
        }
        CP_COMMIT();
      }
      float acc[4] = {};
      #pragma unroll
      for (int kc2 = 0; kc2 < 2; kc2++) {
        if (kc2 == 0) CP_WAIT(1); else CP_WAIT(0);
        NB_SYNC(1 + wk);
        #pragma unroll
        for (int s = 0; s < 8; s++) {
          int ks = (wk * 2 + kc2) * 8 + s;
          uint32_t Ah[4], Al[4], Bh2[2], Bl2[2];
          uint32_t ao = swz(rA, ks * 2 + cA);
          lsm4(Ah, sb + ACT_HI + ao);
          lsm4(Al, sb + ACT_LO + ao);
          uint32_t bo = swz(cg * 8 + rB8, ks * 2 + cSel);
          lsm2(Bh2, sb + WB_HI + bo);
          lsm2(Bl2, sb + WB_LO + bo);
          mma_bf16(acc, Ah, Bh2);
          mma_bf16(acc, Ah, Bl2);
          mma_bf16(acc, Al, Bh2);
        }
      }
      if (w >= 4) {
        int base = (w - 4) * 160 + lid * 5;
        #pragma unroll
        for (int e = 0; e < 4; e++) scr[base + e] = acc[e];
      }
      __syncthreads();
      if (w < 4) {
        int base = w * 160 + lid * 5;
        #pragma unroll
        for (int e = 0; e < 4; e++) acc[e] += scr[base + e];
        #pragma unroll
        for (int rr = 0; rr < 2; rr++) {
          int m = (rr == 0) ? m1 : m2;
          float h0x = hk[rr].x, h0y = hk[rr].y;
          float hp0 = tanhf(ghk[rr * 2 + 0] + acc[rr * 2 + 0]);
          float hp1 = tanhf(ghk[rr * 2 + 1] + acc[rr * 2 + 1]);
          float hn0 = fminf(fmaxf(fmaf(zk[rr * 2 + 0], hp0 - h0x, h0x), -5.f), 5.f);
          float hn1 = fminf(fmaxf(fmaf(zk[rr * 2 + 1], hp1 - h0y, h0y), -5.f), 5.f);
          hk[rr].x = hn0; hk[rr].y = hn1;
          __nv_bfloat162 ph2, pl2;
          ph2.x = __float2bfloat16(hn0); ph2.y = __float2bfloat16(hn1);
          pl2.x = __float2bfloat16(hn0 - __bfloat162float(ph2.x));
          pl2.y = __float2bfloat16(hn1 - __bfloat162float(ph2.y));
          *(__nv_bfloat162*)&g_hh[m * 512 + un] = ph2;
          *(__nv_bfloat162*)&g_hl[m * 512 + un] = pl2;
          size_t ho = (size_t)(t - 1) * (B_ * H_) + m * 512 + un;
          *(__nv_bfloat162*)&g_histh[ho] = ph2;
          *(__nv_bfloat162*)&g_histl[ho] = pl2;
        }
      }
    }
    gbar(grp);
  }
}

// ---------------- final projection: out[:,1..,:] = hist @ Wo + bo (bf16x3 MMA) ----------------
__global__ void __launch_bounds__(256)
proj_kernel(float* __restrict__ out, const float* __restrict__ bo) {
  extern __shared__ char dsm[];
  const uint32_t sb = smem_u32(dsm);
  const int tid = threadIdx.x, w = tid >> 5, lid = tid & 31;
  const int g = lid >> 2, tig = lid & 3;
  const int by = blockIdx.y;
  const int n0 = blockIdx.x * 128;
  const int wm = (w & 3) * 32;
  const int wn = (w >> 2) * 64;
  const size_t mbase = (size_t)by * 128;
  float acc[2][8][4] = {};

  #pragma unroll 1
  for (int kc = 0; kc < 8; kc++) {
    if (kc == 0) {
      #pragma unroll
      for (int i = 0; i < 4; i++) {
        int idx = tid + i * 256, r = idx >> 3, c = idx & 7;
        uint32_t sw = swz128(r, c);
        size_t eA = (mbase + r) * 512 + c * 8;
        int eB = (n0 + r) * 512 + c * 8;
        cp16(sb + sw, &g_histh[eA]);
        cp16(sb + 16384 + sw, &g_histl[eA]);
        cp16(sb + 32768 + sw, &g_Woth[eB]);
        cp16(sb + 49152 + sw, &g_Wotl[eB]);
      }
      CP_COMMIT();
    }
    if (kc < 7) {
      uint32_t base = sb + ((kc + 1) & 1) * 65536;
      int ko = (kc + 1) * 64;
      #pragma unroll
      for (int i = 0; i < 4; i++) {
        int idx = tid + i * 256, r = idx >> 3, c = idx & 7;
        uint32_t sw = swz128(r, c);
        size_t eA = (mbase + r) * 512 + ko + c * 8;
        int eB = (n0 + r) * 512 + ko + c * 8;
        cp16(base + sw, &g_histh[eA]);
        cp16(base + 16384 + sw, &g_histl[eA]);
        cp16(base + 32768 + sw, &g_Woth[eB]);
        cp16(base + 49152 + sw, &g_Wotl[eB]);
      }
      CP_COMMIT();
      CP_WAIT(1);
    } else {
      CP_WAIT(0);
    }
    __syncthreads();
    uint32_t base = sb + (kc & 1) * 65536;
    #pragma unroll
    for (int s = 0; s < 4; s++) {
      int cA = 2 * s + (lid >> 4);
      int cB = 2 * s + ((lid >> 3) & 1);
      uint32_t Ah[2][4], Al[2][4];
      #pragma unroll
      for (int mt = 0; mt < 2; mt++) {
        int rA = wm + mt * 16 + (lid & 15);
        uint32_t aAddr = base + swz128(rA, cA);
        lsm4(Ah[mt], aAddr);
        lsm4(Al[mt], aAddr + 16384);
      }
      #pragma unroll
      for (int p = 0; p < 4; p++) {
        int rB = wn + p * 16 + (lid & 7) + ((lid >> 4) << 3);
        uint32_t bAddr = base + 32768 + swz128(rB, cB);
        uint32_t Bh[4], Bl[4];
        lsm4(Bh, bAddr);
        lsm4(Bl, bAddr + 16384);
        #pragma unroll
        for (int mt = 0; mt < 2; mt++) {
          mma_bf16(acc[mt][2 * p], Ah[mt], Bh);
          mma_bf16(acc[mt][2 * p], Ah[mt], Bl);
          mma_bf16(acc[mt][2 * p], Al[mt], Bh);
          mma_bf16(acc[mt][2 * p + 1], Ah[mt], Bh + 2);
          mma_bf16(acc[mt][2 * p + 1], Ah[mt], Bl + 2);
          mma_bf16(acc[mt][2 * p + 1], Al[mt], Bh + 2);
        }
      }
    }
    __syncthreads();
  }
  #pragma unroll
  for (int mt = 0; mt < 2; mt++) {
    #pragma unroll
    for (int nt = 0; nt < 8; nt++) {
      int n = n0 + wn + nt * 8 + tig * 2;
      float2 bb = *(const float2*)&bo[n];
      #pragma unroll
      for (int rr = 0; rr < 2; rr++) {
        int b = wm + mt * 16 + g + rr * 8;
        float v0 = acc[mt][nt][rr * 2 + 0] + bb.x;
        float v1 = acc[mt][nt][rr * 2 + 1] + bb.y;
        *(float2*)&out[(size_t)b * ((size_t)T_ * D_) + (size_t)(by + 1) * D_ + n] =
            make_float2(v0, v1);
      }
    }
  }
}

// ---------------- fused setup kernels ----------------
struct EpiFold {
  const float *Ur, *Uz;
  __device__ __forceinline__ void operator()(int m, int n, float v) const {
    if (n < H_)            v += Ur[m * H_ + n];
    else if (n < 2 * H_)   v += Uz[m * H_ + (n - H_)];
    g_Acat[m * NG_ + n] = v;
  }
};
struct EpiStep1 {
  __device__ __forceinline__ void operator()(int m, int n, float v) const {
    v += g_bpack[H_ + n];
    if (n < H_) g_Gz[m * H_ + n] = v;
    else        g_Gh[m * H_ + (n - H_)] = v;
  }
};

template <class Epi>
__device__ __forceinline__ void gemm_body(const float* __restrict__ A,
                                          const float* __restrict__ Bm,
                                          int K, int ldb, Epi epi, int bxi, int byi) {
  constexpr int BM = 32, BK = 32, BN = 64, NTHR = 256;
  __shared__ __align__(16) float As[BK][BM + 1];
  __shared__ __align__(16) float Bs[BK][BN];
  const int tid = threadIdx.x;
  const int bm = byi * BM;
  const int bn = bxi * BN;
  const int tx = tid % (BN / 4);
  const int ty = tid / (BN / 4);
  float acc[2][4] = {};
  for (int k0 = 0; k0 < K; k0 += BK) {
    #pragma unroll
    for (int i = tid * 4; i < BM * BK; i += NTHR * 4) {
      int m = i / BK, k = i % BK;
      float4 v = *(const float4*)(A + (size_t)(bm + m) * K + k0 + k);
      As[k + 0][m] = v.x; As[k + 1][m] = v.y; As[k + 2][m] = v.z; As[k + 3][m] = v.w;
    }
    #pragma unroll
    for (int i = tid * 4; i < BK * BN; i += NTHR * 4) {
      int k = i / BN, n = i % BN;
      *(float4*)&Bs[k][n] = *(const float4*)(Bm + (size_t)(k0 + k) * ldb + bn + n);
    }
    __syncthreads();
    #pragma unroll
    for (int kk = 0; kk < BK; kk++) {
      float a0 = As[kk][ty * 2 + 0];
      float a1 = As[kk][ty * 2 + 1];
      float4 b4 = *(float4*)&Bs[kk][tx * 4];
      acc[0][0] = fmaf(a0, b4.x, acc[0][0]);
      acc[0][1] = fmaf(a0, b4.y, acc[0][1]);
      acc[0][2] = fmaf(a0, b4.z, acc[0][2]);
      acc[0][3] = fmaf(a0, b4.w, acc[0][3]);
      acc[1][0] = fmaf(a1, b4.x, acc[1][0]);
      acc[1][1] = fmaf(a1, b4.y, acc[1][1]);
      acc[1][2] = fmaf(a1, b4.z, acc[1][2]);
      acc[1][3] = fmaf(a1, b4.w, acc[1][3]);
    }
    __syncthreads();
  }
  #pragma unroll
  for (int i = 0; i < 2; i++)
    #pragma unroll
    for (int j = 0; j < 4; j++)
      epi(bm + ty * 2 + i, bn + tx * 4 + j, acc[i][j]);
}

// launch slot 0: pack weights + reset barriers
__global__ void pack_kernel(const float* __restrict__ Wr, const float* __restrict__ Wz,
                            const float* __restrict__ Wh, const float* __restrict__ br,
                            const float* __restrict__ bz, const float* __restrict__ bh) {
  int idx = blockIdx.x * blockDim.x + threadIdx.x;
  if (idx < 4) { g_grpArr[idx * 32] = 0; g_grpGen[idx * 32] = 0; }
  if (idx < NG_) {
    int sel = idx >> 9, jl = idx & 511;
    g_bpack[idx] = (sel == 0) ? br[jl] : (sel == 1) ? bz[jl] : bh[jl];
  }
  if (idx < D_ * NG_) {
    int d = idx / NG_, j = idx % NG_;
    int sel = j >> 9, jl = j & 511;
    const float* W = (sel == 0) ? Wr : (sel == 1) ? Wz : Wh;
    g_Wpack[idx] = W[d * H_ + jl];
  }
}

// launch slot 1: fold-GEMM (384 blk) + step1-GEMM (64 blk) + ccat (192 blk)
__global__ void __launch_bounds__(256)
setup1_kernel(const float* __restrict__ Wo, const float* __restrict__ Ur,
              const float* __restrict__ Uz, const float* __restrict__ inputs,
              const float* __restrict__ bo) {
  int b = blockIdx.x;
  if (b < 384) {
    gemm_body(Wo, g_Wpack, D_, NG_, EpiFold{Ur, Uz}, b % 24, b / 24);
  } else if (b < 448) {
    int bb = b - 384;
    gemm_body(inputs, g_Wpack + H_, D_, NG_, EpiStep1{}, bb % 16, bb / 16);
  } else {
    int w = (b - 448) * 8 + (threadIdx.x >> 5);
    int lane = threadIdx.x & 31;
    if (w < NG_) {
      float acc = 0.f;
      for (int d = lane; d < D_; d += 32)
        acc = fmaf(bo[d], g_Wpack[(size_t)d * NG_ + w], acc);
      #pragma unroll
      for (int o = 16; o; o >>= 1) acc += __shfl_xor_sync(0xffffffffu, acc, o);
      if (lane == 0) g_ccat[w] = acc + g_bpack[w];
    }
  }
}

// launch slot 2: PERMUTED bf16 splits (3072 blk) + combine1 (256 blk)
__global__ void __launch_bounds__(256)
setup2_kernel(const float* __restrict__ Uh, const float* __restrict__ Wo) {
  int b = blockIdx.x;
  if (b < 3072) {
    int idx = b * 256 + threadIdx.x;
    if (idx < NG_ * H_) {
      int row = idx >> 9, k = idx & 511;
      int p = row / 48, c = row % 48;
      int gidx = c / 24, j = c % 24;
      int u = p * 16 + gidx * 8 + (j & 7);
      int gate = j >> 3;                 // 0:z 1:hcand 2:r
      int src = (gate == 0) ? 512 + u : (gate == 1) ? 1024 + u : u;
      float x = g_Acat[(size_t)k * NG_ + src];
      __nv_bfloat16 hi = __float2bfloat16(x);
      g_Ath[idx] = hi;
      g_Atl[idx] = __float2bfloat16(x - __bfloat162float(hi));
      if (k == 0) g_ccatP[row] = g_ccat[src];
    }
    if (idx < H_ * H_) {
      int n = idx >> 9, k = idx & 511;
      float x = Uh[(size_t)k * H_ + n];
      __nv_bfloat16 hi = __float2bfloat16(x);
      g_Uth[idx] = hi;
      g_Utl[idx] = __float2bfloat16(x - __bfloat162float(hi));
      float y = Wo[(size_t)k * D_ + n];
      __nv_bfloat16 hi2 = __float2bfloat16(y);
      g_Woth[idx] = hi2;
      g_Wotl[idx] = __float2bfloat16(y - __bfloat162float(hi2));
    }
  } else {
    int idx = (b - 3072) * 256 + threadIdx.x;
    if (idx < B_ * H_) {
      float z  = sigmoidf_(g_Gz[idx]);
      float hp = tanhf(g_Gh[idx]);
      float hn = fminf(fmaxf(z * hp, -5.f), 5.f);
      g_h[idx] = hn;
      __nv_bfloat16 hi = __float2bfloat16(hn);
      __nv_bfloat16 lo = __float2bfloat16(hn - __bfloat162float(hi));
      g_hh[idx] = hi;
      g_hl[idx] = lo;
      g_histh[idx] = hi;
      g_histl[idx] = lo;
    }
  }
}

__global__ void copy0_kernel(const float* __restrict__ inputs, float* __restrict__ out) {
  int idx = blockIdx.x * blockDim.x + threadIdx.x;
  if (idx >= B_ * D_) return;
  int b = idx / D_, d = idx % D_;
  out[(size_t)b * ((size_t)T_ * D_) + d] = inputs[idx];
}

// ---------------- launch ----------------
extern "C" void kernel_launch(void* const* d_in, const int* in_sizes, int n_in,
                              void* d_out, int out_size) {
  const float* inputs = (const float*)d_in[0];
  const float* Wz = (const float*)d_in[1];
  const float* Wr = (const float*)d_in[2];
  const float* Wh = (const float*)d_in[3];
  const float* Uz = (const float*)d_in[4];
  const float* Ur = (const float*)d_in[5];
  const float* Uh = (const float*)d_in[6];
  const float* bz = (const float*)d_in[7];
  const float* br = (const float*)d_in[8];
  const float* bh = (const float*)d_in[9];
  const float* Wo = (const float*)d_in[10];
  const float* bo = (const float*)d_in[11];
  float* out = (float*)d_out;

  cudaFuncSetAttribute(proj_kernel, cudaFuncAttributeMaxDynamicSharedMemorySize, 131072);
  cudaFuncSetAttribute(recur_kernel, cudaFuncAttributeMaxDynamicSharedMemorySize, RSMEM);

  // slot 0: pack + barrier reset
  pack_kernel<<<(D_ * NG_ + 255) / 256, 256>>>(Wr, Wz, Wh, br, bz, bh);
  // slot 1: fold + ccat + step1 (fused)
  setup1_kernel<<<640, 256>>>(Wo, Ur, Uz, inputs, bo);
  // slot 2: permuted bf16 splits + combine1 (fused)
  setup2_kernel<<<3328, 256>>>(Uh, Wo);
  // slot 3 (ncu-profiled slot): persistent recurrence (R12 structure, cheaper barrier)
  recur_kernel<<<NCTA, 256, RSMEM>>>();
  // slot 4: t=0 output copy
  copy0_kernel<<<(B_ * D_ + 255) / 256, 256>>>(inputs, out);
  // slot 5: deferred projection
  proj_kernel<<<dim3(4, T_ - 1), 256, 131072>>>(out, bo);
}

// round 15
// speedup vs baseline: 1.6610x; 1.1410x over previous
#include <cuda_runtime.h>
#include <cuda_bf16.h>
#include <math.h>
#include <stdint.h>

#define B_  128
#define D_  512
#define H_  512
#define T_  500
#define NG_ 1536   // 3*H : [r|z|h]
#define NCTA 128

// ---------------- static device scratch ----------------
__device__ float g_Wpack[D_ * NG_];
__device__ float g_bpack[NG_];
__device__ float g_Acat[H_ * NG_];               // [k=512][g=1536] fp32
__device__ float g_ccat[NG_];
__device__ float g_ccatP[NG_];                   // permuted per-CTA-strip bias
__device__ float g_h[B_ * H_];                   // init only (loop keeps h in regs)
__device__ float g_Gz[B_ * H_];                  // init only
__device__ float g_Gh[B_ * H_];                  // init only
__device__ __nv_bfloat16 g_Ath[NG_ * H_];        // permuted Acat^T hi [strip rows][k]
__device__ __nv_bfloat16 g_Atl[NG_ * H_];
__device__ __nv_bfloat16 g_Uth[H_ * H_];         // Uh^T hi [n][k]
__device__ __nv_bfloat16 g_Utl[H_ * H_];
__device__ __nv_bfloat16 g_Woth[H_ * D_];        // Wo^T hi [n][k]
__device__ __nv_bfloat16 g_Wotl[H_ * D_];
__device__ __nv_bfloat16 g_hh[B_ * H_];          // h split (exchange)
__device__ __nv_bfloat16 g_hl[B_ * H_];
__device__ __nv_bfloat16 g_rhh[B_ * H_];         // (r*h) split (exchange)
__device__ __nv_bfloat16 g_rhl[B_ * H_];
__device__ __nv_bfloat16 g_histh[(size_t)(T_ - 1) * B_ * H_];
__device__ __nv_bfloat16 g_histl[(size_t)(T_ - 1) * B_ * H_];

// per-m-group barrier arrive counters (monotonic), 128B apart
__device__ unsigned g_grpArr[4 * 32];

__device__ __forceinline__ float sigmoidf_(float x) { return 1.f / (1.f + __expf(-x)); }

__device__ __forceinline__ void atom_add_rel(unsigned* p, unsigned v) {
  unsigned old;
  asm volatile("atom.add.release.gpu.u32 %0, [%1], %2;"
               : "=r"(old) : "l"(p), "r"(v) : "memory");
}
__device__ __forceinline__ unsigned ld_acq(const unsigned* p) {
  unsigned v;
  asm volatile("ld.global.acquire.gpu.u32 %0, [%1];" : "=r"(v) : "l"(p) : "memory");
  return v;
}

// group barrier: poll the monotonic arrive counter directly (no release-store hop);
// per-warp wait so warps proceed independently after the count lands.
__device__ __forceinline__ void gbar(int grp, unsigned target) {
  __syncthreads();                                   // all CTA work done / smem reads done
  if (threadIdx.x == 0) atom_add_rel(&g_grpArr[grp * 32], 1u);
  if ((threadIdx.x & 31) == 0) {
    while (ld_acq(&g_grpArr[grp * 32]) < target) {}
  }
  __syncwarp();
}

// ---------------- mma.sync / ldmatrix / cp.async primitives ----------------
__device__ __forceinline__ uint32_t smem_u32(const void* p) {
  uint32_t a;
  asm("{ .reg .u64 t; cvta.to.shared.u64 t, %1; cvt.u32.u64 %0, t; }" : "=r"(a) : "l"(p));
  return a;
}
__device__ __forceinline__ void cp16(uint32_t dst, const void* src) {
  asm volatile("cp.async.cg.shared.global [%0], [%1], 16;" :: "r"(dst), "l"(src));
}
#define CP_COMMIT() asm volatile("cp.async.commit_group;" ::: "memory")
#define CP_WAIT(n)  asm volatile("cp.async.wait_group %0;" :: "n"(n) : "memory")
#define NB_SYNC(id) asm volatile("bar.sync %0, 128;" :: "r"(id) : "memory")
__device__ __forceinline__ void lsm4(uint32_t* r, uint32_t a) {
  asm volatile("ldmatrix.sync.aligned.m8n8.x4.shared.b16 {%0,%1,%2,%3}, [%4];"
               : "=r"(r[0]), "=r"(r[1]), "=r"(r[2]), "=r"(r[3]) : "r"(a));
}
__device__ __forceinline__ void lsm2(uint32_t* r, uint32_t a) {
  asm volatile("ldmatrix.sync.aligned.m8n8.x2.shared.b16 {%0,%1}, [%2];"
               : "=r"(r[0]), "=r"(r[1]) : "r"(a));
}
__device__ __forceinline__ void mma_bf16(float* d, const uint32_t* a, const uint32_t* b) {
  asm volatile(
      "mma.sync.aligned.m16n8k16.row.col.f32.bf16.bf16.f32 "
      "{%0,%1,%2,%3}, {%4,%5,%6,%7}, {%8,%9}, {%0,%1,%2,%3};"
      : "+f"(d[0]), "+f"(d[1]), "+f"(d[2]), "+f"(d[3])
      : "r"(a[0]), "r"(a[1]), "r"(a[2]), "r"(a[3]), "r"(b[0]), "r"(b[1]));
}
__device__ __forceinline__ uint32_t swz(int r, int c) {
  return (uint32_t)(r * 1024 + (((c) ^ (r & 7)) << 4));
}
__device__ __forceinline__ uint32_t swz128(int r, int c) {
  return (uint32_t)(r * 128 + ((c ^ (r & 7)) << 4));
}

// smem offsets for recur kernel (dynamic, 200 KB)
#define WA_HI  0u
#define WA_LO  49152u
#define WB_HI  98304u
#define WB_LO  114688u
#define ACT_HI 131072u
#define ACT_LO 163840u
#define SCR_   196608u
#define RSMEM  204800

// ---------------- persistent recurrence kernel: 128 CTAs x 256 thr ----------------
__global__ void __launch_bounds__(256)
recur_kernel() {
  extern __shared__ char smem[];
  const uint32_t sb = smem_u32(smem);
  float* scr = (float*)(smem + SCR_);
  const int tid = threadIdx.x, bid = blockIdx.x;
  const int w = tid >> 5, lid = tid & 31;
  const int g = lid >> 2, tig = lid & 3;
  const int wpos = w & 3, wk = w >> 2;
  const int grp = bid & 3;
  const int m0 = grp * 32;
  const int strip = bid >> 2;           // [0,32)
  const int n0A = strip * 48;
  const int n0B = strip * 16;
  const int wm = (wpos & 1) * 16;
  const int cg = wpos >> 1;
  const int wnA = cg * 24;
  const int rA = wm + (lid & 15);
  const int rB16 = (lid & 7) + ((lid >> 4) << 3);
  const int rB8 = lid & 7;
  const int cA = lid >> 4;
  const int cSel = (lid >> 3) & 1;
  const int m1 = m0 + wm + g, m2 = m1 + 8;
  const int half = tid >> 7, ltid = tid & 127;
  const int un = n0B + cg * 8 + tig * 2;

  // ---- one-time: load weight strips into smem ----
  #pragma unroll
  for (int i = 0; i < 12; i++) {
    int idx = tid + i * 256, r = idx >> 6, c = idx & 63;
    size_t go = (size_t)(n0A + r) * 512 + c * 8;
    cp16(sb + WA_HI + swz(r, c), &g_Ath[go]);
    cp16(sb + WA_LO + swz(r, c), &g_Atl[go]);
  }
  #pragma unroll
  for (int i = 0; i < 4; i++) {
    int idx = tid + i * 256, r = idx >> 6, c = idx & 63;
    size_t go = (size_t)(n0B + r) * 512 + c * 8;
    cp16(sb + WB_HI + swz(r, c), &g_Uth[go]);
    cp16(sb + WB_LO + swz(r, c), &g_Utl[go]);
  }
  CP_COMMIT();
  CP_WAIT(0);
  __syncthreads();

  // persistent per-thread state + hoisted biases (warps 0-3)
  float zk[4], ghk[4];
  float2 hk[2] = {make_float2(0.f, 0.f), make_float2(0.f, 0.f)};
  float2 ccz = make_float2(0.f, 0.f), cch = ccz, ccr = ccz;
  if (w < 4) {
    hk[0] = *(const float2*)&g_h[m1 * 512 + un];
    hk[1] = *(const float2*)&g_h[m2 * 512 + un];
    int rbase = n0A + cg * 24 + tig * 2;
    ccz = *(const float2*)&g_ccatP[rbase + 0];
    cch = *(const float2*)&g_ccatP[rbase + 8];
    ccr = *(const float2*)&g_ccatP[rbase + 16];
  }

  unsigned bt = 0;   // barrier target (32 per phase)

  for (int t = 2; t < T_; t++) {
    // ================= Stage A =================
    {
      #pragma unroll
      for (int kc2 = 0; kc2 < 2; kc2++) {
        int kc = half * 2 + kc2;
        #pragma unroll
        for (int i = 0; i < 4; i++) {
          int idx = ltid + i * 128, r = idx >> 4, cs = idx & 15;
          int go = (m0 + r) * 512 + kc * 128 + cs * 8;
          cp16(sb + ACT_HI + swz(r, kc * 16 + cs), &g_hh[go]);
          cp16(sb + ACT_LO + swz(r, kc * 16 + cs), &g_hl[go]);
        }
        CP_COMMIT();
      }
      float acc0[4] = {}, acc1[4] = {}, acc2[4] = {};
      #pragma unroll
      for (int kc2 = 0; kc2 < 2; kc2++) {
        if (kc2 == 0) CP_WAIT(1); else CP_WAIT(0);
        NB_SYNC(1 + wk);
        #pragma unroll
        for (int s = 0; s < 8; s++) {
          int ks = (wk * 2 + kc2) * 8 + s;
          uint32_t Ah[4], Al[4], Bh[4], Bl[4], Bh2[2], Bl2[2];
          uint32_t ao = swz(rA, ks * 2 + cA);
          lsm4(Ah, sb + ACT_HI + ao);
          lsm4(Al, sb + ACT_LO + ao);
          uint32_t bo = swz(wnA + rB16, ks * 2 + cSel);
          lsm4(Bh, sb + WA_HI + bo);
          lsm4(Bl, sb + WA_LO + bo);
          uint32_t bo2 = swz(wnA + 16 + rB8, ks * 2 + cSel);
          lsm2(Bh2, sb + WA_HI + bo2);
          lsm2(Bl2, sb + WA_LO + bo2);
          mma_bf16(acc0, Ah, Bh);     mma_bf16(acc0, Ah, Bl);     mma_bf16(acc0, Al, Bh);
          mma_bf16(acc1, Ah, Bh + 2); mma_bf16(acc1, Ah, Bl + 2); mma_bf16(acc1, Al, Bh + 2);
          mma_bf16(acc2, Ah, Bh2);    mma_bf16(acc2, Ah, Bl2);    mma_bf16(acc2, Al, Bh2);
        }
      }
      if (w >= 4) {
        int base = (w - 4) * 416 + lid * 13;
        #pragma unroll
        for (int e = 0; e < 4; e++) scr[base + e] = acc0[e];
        #pragma unroll
        for (int e = 0; e < 4; e++) scr[base + 4 + e] = acc1[e];
        #pragma unroll
        for (int e = 0; e < 4; e++) scr[base + 8 + e] = acc2[e];
      }
      __syncthreads();
      if (w < 4) {
        int base = w * 416 + lid * 13;
        #pragma unroll
        for (int e = 0; e < 4; e++) acc0[e] += scr[base + e];
        #pragma unroll
        for (int e = 0; e < 4; e++) acc1[e] += scr[base + 4 + e];
        #pragma unroll
        for (int e = 0; e < 4; e++) acc2[e] += scr[base + 8 + e];
        zk[0] = sigmoidf_(acc0[0] + ccz.x); zk[1] = sigmoidf_(acc0[1] + ccz.y);
        zk[2] = sigmoidf_(acc0[2] + ccz.x); zk[3] = sigmoidf_(acc0[3] + ccz.y);
        ghk[0] = acc1[0] + cch.x; ghk[1] = acc1[1] + cch.y;
        ghk[2] = acc1[2] + cch.x; ghk[3] = acc1[3] + cch.y;
        float rh00 = sigmoidf_(acc2[0] + ccr.x) * hk[0].x;
        float rh01 = sigmoidf_(acc2[1] + ccr.y) * hk[0].y;
        float rh10 = sigmoidf_(acc2[2] + ccr.x) * hk[1].x;
        float rh11 = sigmoidf_(acc2[3] + ccr.y) * hk[1].y;
        __nv_bfloat162 ph2, pl2;
        ph2.x = __float2bfloat16(rh00); ph2.y = __float2bfloat16(rh01);
        pl2.x = __float2bfloat16(rh00 - __bfloat162float(ph2.x));
        pl2.y = __float2bfloat16(rh01 - __bfloat162float(ph2.y));
        *(__nv_bfloat162*)&g_rhh[m1 * 512 + un] = ph2;
        *(__nv_bfloat162*)&g_rhl[m1 * 512 + un] = pl2;
        ph2.x = __float2bfloat16(rh10); ph2.y = __float2bfloat16(rh11);
        pl2.x = __float2bfloat16(rh10 - __bfloat162float(ph2.x));
        pl2.y = __float2bfloat16(rh11 - __bfloat162float(ph2.y));
        *(__nv_bfloat162*)&g_rhh[m2 * 512 + un] = ph2;
        *(__nv_bfloat162*)&g_rhl[m2 * 512 + un] = pl2;
      }
    }
    bt += 32;
    gbar(grp, bt);

    // ================= Stage B =================
    {
      #pragma unroll
      for (int kc2 = 0; kc2 < 2; kc2++) {
        int kc = half * 2 + kc2;
        #pragma unroll
        for (int i = 0; i < 4; i++) {
          int idx = ltid + i * 128, r = idx >> 4, cs = idx & 15;
          int go = (m0 + r) * 512 + kc * 128 + cs * 8;
          cp16(sb + ACT_HI + swz(r, kc * 16 + cs), &g_rhh[go]);
          cp16(sb + ACT_LO + swz(r, kc * 16 + cs), &g_rhl[go]);
        }
        CP_COMMIT();
      }
      float acc[4] = {};
      #pragma unroll
      for (int kc2 = 0; kc2 < 2; kc2++) {
        if (kc2 == 0) CP_WAIT(1); else CP_WAIT(0);
        NB_SYNC(1 + wk);
        #pragma unroll
        for (int s = 0; s < 8; s++) {
          int ks = (wk * 2 + kc2) * 8 + s;
          uint32_t Ah[4], Al[4], Bh2[2], Bl2[2];
          uint32_t ao = swz(rA, ks * 2 + cA);
          lsm4(Ah, sb + ACT_HI + ao);
          lsm4(Al, sb + ACT_LO + ao);
          uint32_t bo = swz(cg * 8 + rB8, ks * 2 + cSel);
          lsm2(Bh2, sb + WB_HI + bo);
          lsm2(Bl2, sb + WB_LO + bo);
          mma_bf16(acc, Ah, Bh2);
          mma_bf16(acc, Ah, Bl2);
          mma_bf16(acc, Al, Bh2);
        }
      }
      if (w >= 4) {
        int base = (w - 4) * 160 + lid * 5;
        #pragma unroll
        for (int e = 0; e < 4; e++) scr[base + e] = acc[e];
      }
      __syncthreads();
      if (w < 4) {
        int base = w * 160 + lid * 5;
        #pragma unroll
        for (int e = 0; e < 4; e++) acc[e] += scr[base + e];
        #pragma unroll
        for (int rr = 0; rr < 2; rr++) {
          int m = (rr == 0) ? m1 : m2;
          float h0x = hk[rr].x, h0y = hk[rr].y;
          float hp0 = tanhf(ghk[rr * 2 + 0] + acc[rr * 2 + 0]);
          float hp1 = tanhf(ghk[rr * 2 + 1] + acc[rr * 2 + 1]);
          float hn0 = fminf(fmaxf(fmaf(zk[rr * 2 + 0], hp0 - h0x, h0x), -5.f), 5.f);
          float hn1 = fminf(fmaxf(fmaf(zk[rr * 2 + 1], hp1 - h0y, h0y), -5.f), 5.f);
          hk[rr].x = hn0; hk[rr].y = hn1;
          __nv_bfloat162 ph2, pl2;
          ph2.x = __float2bfloat16(hn0); ph2.y = __float2bfloat16(hn1);
          pl2.x = __float2bfloat16(hn0 - __bfloat162float(ph2.x));
          pl2.y = __float2bfloat16(hn1 - __bfloat162float(ph2.y));
          *(__nv_bfloat162*)&g_hh[m * 512 + un] = ph2;
          *(__nv_bfloat162*)&g_hl[m * 512 + un] = pl2;
          size_t ho = (size_t)(t - 1) * (B_ * H_) + m * 512 + un;
          *(__nv_bfloat162*)&g_histh[ho] = ph2;
          *(__nv_bfloat162*)&g_histl[ho] = pl2;
        }
      }
    }
    bt += 32;
    gbar(grp, bt);
  }
}

// ---------------- final projection: out[:,1..,:] = hist @ Wo + bo (bf16x3 MMA) ----------------
__global__ void __launch_bounds__(256)
proj_kernel(float* __restrict__ out, const float* __restrict__ bo) {
  extern __shared__ char dsm[];
  const uint32_t sb = smem_u32(dsm);
  const int tid = threadIdx.x, w = tid >> 5, lid = tid & 31;
  const int g = lid >> 2, tig = lid & 3;
  const int by = blockIdx.y;
  const int n0 = blockIdx.x * 128;
  const int wm = (w & 3) * 32;
  const int wn = (w >> 2) * 64;
  const size_t mbase = (size_t)by * 128;
  float acc[2][8][4] = {};

  #pragma unroll 1
  for (int kc = 0; kc < 8; kc++) {
    if (kc == 0) {
      #pragma unroll
      for (int i = 0; i < 4; i++) {
        int idx = tid + i * 256, r = idx >> 3, c = idx & 7;
        uint32_t sw = swz128(r, c);
        size_t eA = (mbase + r) * 512 + c * 8;
        int eB = (n0 + r) * 512 + c * 8;
        cp16(sb + sw, &g_histh[eA]);
        cp16(sb + 16384 + sw, &g_histl[eA]);
        cp16(sb + 32768 + sw, &g_Woth[eB]);
        cp16(sb + 49152 + sw, &g_Wotl[eB]);
      }
      CP_COMMIT();
    }
    if (kc < 7) {
      uint32_t base = sb + ((kc + 1) & 1) * 65536;
      int ko = (kc + 1) * 64;
      #pragma unroll
      for (int i = 0; i < 4; i++) {
        int idx = tid + i * 256, r = idx >> 3, c = idx & 7;
        uint32_t sw = swz128(r, c);
        size_t eA = (mbase + r) * 512 + ko + c * 8;
        int eB = (n0 + r) * 512 + ko + c * 8;
        cp16(base + sw, &g_histh[eA]);
        cp16(base + 16384 + sw, &g_histl[eA]);
        cp16(base + 32768 + sw, &g_Woth[eB]);
        cp16(base + 49152 + sw, &g_Wotl[eB]);
      }
      CP_COMMIT();
      CP_WAIT(1);
    } else {
      CP_WAIT(0);
    }
    __syncthreads();
    uint32_t base = sb + (kc & 1) * 65536;
    #pragma unroll
    for (int s = 0; s < 4; s++) {
      int cA = 2 * s + (lid >> 4);
      int cB = 2 * s + ((lid >> 3) & 1);
      uint32_t Ah[2][4], Al[2][4];
      #pragma unroll
      for (int mt = 0; mt < 2; mt++) {
        int rA = wm + mt * 16 + (lid & 15);
        uint32_t aAddr = base + swz128(rA, cA);
        lsm4(Ah[mt], aAddr);
        lsm4(Al[mt], aAddr + 16384);
      }
      #pragma unroll
      for (int p = 0; p < 4; p++) {
        int rB = wn + p * 16 + (lid & 7) + ((lid >> 4) << 3);
        uint32_t bAddr = base + 32768 + swz128(rB, cB);
        uint32_t Bh[4], Bl[4];
        lsm4(Bh, bAddr);
        lsm4(Bl, bAddr + 16384);
        #pragma unroll
        for (int mt = 0; mt < 2; mt++) {
          mma_bf16(acc[mt][2 * p], Ah[mt], Bh);
          mma_bf16(acc[mt][2 * p], Ah[mt], Bl);
          mma_bf16(acc[mt][2 * p], Al[mt], Bh);
          mma_bf16(acc[mt][2 * p + 1], Ah[mt], Bh + 2);
          mma_bf16(acc[mt][2 * p + 1], Ah[mt], Bl + 2);
          mma_bf16(acc[mt][2 * p + 1], Al[mt], Bh + 2);
        }
      }
    }
    __syncthreads();
  }
  #pragma unroll
  for (int mt = 0; mt < 2; mt++) {
    #pragma unroll
    for (int nt = 0; nt < 8; nt++) {
      int n = n0 + wn + nt * 8 + tig * 2;
      float2 bb = *(const float2*)&bo[n];
      #pragma unroll
      for (int rr = 0; rr < 2; rr++) {
        int b = wm + mt * 16 + g + rr * 8;
        float v0 = acc[mt][nt][rr * 2 + 0] + bb.x;
        float v1 = acc[mt][nt][rr * 2 + 1] + bb.y;
        *(float2*)&out[(size_t)b * ((size_t)T_ * D_) + (size_t)(by + 1) * D_ + n] =
            make_float2(v0, v1);
      }
    }
  }
}

// ---------------- fused setup kernels ----------------
struct EpiFold {
  const float *Ur, *Uz;
  __device__ __forceinline__ void operator()(int m, int n, float v) const {
    if (n < H_)            v += Ur[m * H_ + n];
    else if (n < 2 * H_)   v += Uz[m * H_ + (n - H_)];
    g_Acat[m * NG_ + n] = v;
  }
};
struct EpiStep1 {
  __device__ __forceinline__ void operator()(int m, int n, float v) const {
    v += g_bpack[H_ + n];
    if (n < H_) g_Gz[m * H_ + n] = v;
    else        g_Gh[m * H_ + (n - H_)] = v;
  }
};

template <class Epi>
__device__ __forceinline__ void gemm_body(const float* __restrict__ A,
                                          const float* __restrict__ Bm,
                                          int K, int ldb, Epi epi, int bxi, int byi) {
  constexpr int BM = 32, BK = 32, BN = 64, NTHR = 256;
  __shared__ __align__(16) float As[BK][BM + 1];
  __shared__ __align__(16) float Bs[BK][BN];
  const int tid = threadIdx.x;
  const int bm = byi * BM;
  const int bn = bxi * BN;
  const int tx = tid % (BN / 4);
  const int ty = tid / (BN / 4);
  float acc[2][4] = {};
  for (int k0 = 0; k0 < K; k0 += BK) {
    #pragma unroll
    for (int i = tid * 4; i < BM * BK; i += NTHR * 4) {
      int m = i / BK, k = i % BK;
      float4 v = *(const float4*)(A + (size_t)(bm + m) * K + k0 + k);
      As[k + 0][m] = v.x; As[k + 1][m] = v.y; As[k + 2][m] = v.z; As[k + 3][m] = v.w;
    }
    #pragma unroll
    for (int i = tid * 4; i < BK * BN; i += NTHR * 4) {
      int k = i / BN, n = i % BN;
      *(float4*)&Bs[k][n] = *(const float4*)(Bm + (size_t)(k0 + k) * ldb + bn + n);
    }
    __syncthreads();
    #pragma unroll
    for (int kk = 0; kk < BK; kk++) {
      float a0 = As[kk][ty * 2 + 0];
      float a1 = As[kk][ty * 2 + 1];
      float4 b4 = *(float4*)&Bs[kk][tx * 4];
      acc[0][0] = fmaf(a0, b4.x, acc[0][0]);
      acc[0][1] = fmaf(a0, b4.y, acc[0][1]);
      acc[0][2] = fmaf(a0, b4.z, acc[0][2]);
      acc[0][3] = fmaf(a0, b4.w, acc[0][3]);
      acc[1][0] = fmaf(a1, b4.x, acc[1][0]);
      acc[1][1] = fmaf(a1, b4.y, acc[1][1]);
      acc[1][2] = fmaf(a1, b4.z, acc[1][2]);
      acc[1][3] = fmaf(a1, b4.w, acc[1][3]);
    }
    __syncthreads();
  }
  #pragma unroll
  for (int i = 0; i < 2; i++)
    #pragma unroll
    for (int j = 0; j < 4; j++)
      epi(bm + ty * 2 + i, bn + tx * 4 + j, acc[i][j]);
}

// launch slot 0: pack weights + reset barriers
__global__ void pack_kernel(const float* __restrict__ Wr, const float* __restrict__ Wz,
                            const float* __restrict__ Wh, const float* __restrict__ br,
                            const float* __restrict__ bz, const float* __restrict__ bh) {
  int idx = blockIdx.x * blockDim.x + threadIdx.x;
  if (idx < 4) g_grpArr[idx * 32] = 0;
  if (idx < NG_) {
    int sel = idx >> 9, jl = idx & 511;
    g_bpack[idx] = (sel == 0) ? br[jl] : (sel == 1) ? bz[jl] : bh[jl];
  }
  if (idx < D_ * NG_) {
    int d = idx / NG_, j = idx % NG_;
    int sel = j >> 9, jl = j & 511;
    const float* W = (sel == 0) ? Wr : (sel == 1) ? Wz : Wh;
    g_Wpack[idx] = W[d * H_ + jl];
  }
}

// launch slot 1: fold-GEMM (384 blk) + step1-GEMM (64 blk) + ccat (192 blk)
__global__ void __launch_bounds__(256)
setup1_kernel(const float* __restrict__ Wo, const float* __restrict__ Ur,
              const float* __restrict__ Uz, const float* __restrict__ inputs,
              const float* __restrict__ bo) {
  int b = blockIdx.x;
  if (b < 384) {
    gemm_body(Wo, g_Wpack, D_, NG_, EpiFold{Ur, Uz}, b % 24, b / 24);
  } else if (b < 448) {
    int bb = b - 384;
    gemm_body(inputs, g_Wpack + H_, D_, NG_, EpiStep1{}, bb % 16, bb / 16);
  } else {
    int w = (b - 448) * 8 + (threadIdx.x >> 5);
    int lane = threadIdx.x & 31;
    if (w < NG_) {
      float acc = 0.f;
      for (int d = lane; d < D_; d += 32)
        acc = fmaf(bo[d], g_Wpack[(size_t)d * NG_ + w], acc);
      #pragma unroll
      for (int o = 16; o; o >>= 1) acc += __shfl_xor_sync(0xffffffffu, acc, o);
      if (lane == 0) g_ccat[w] = acc + g_bpack[w];
    }
  }
}

// launch slot 2: PERMUTED bf16 splits (3072 blk) + combine1 (256 blk)
__global__ void __launch_bounds__(256)
setup2_kernel(const float* __restrict__ Uh, const float* __restrict__ Wo) {
  int b = blockIdx.x;
  if (b < 3072) {
    int idx = b * 256 + threadIdx.x;
    if (idx < NG_ * H_) {
      int row = idx >> 9, k = idx & 511;
      int p = row / 48, c = row % 48;
      int gidx = c / 24, j = c % 24;
      int u = p * 16 + gidx * 8 + (j & 7);
      int gate = j >> 3;                 // 0:z 1:hcand 2:r
      int src = (gate == 0) ? 512 + u : (gate == 1) ? 1024 + u : u;
      float x = g_Acat[(size_t)k * NG_ + src];
      __nv_bfloat16 hi = __float2bfloat16(x);
      g_Ath[idx] = hi;
      g_Atl[idx] = __float2bfloat16(x - __bfloat162float(hi));
      if (k == 0) g_ccatP[row] = g_ccat[src];
    }
    if (idx < H_ * H_) {
      int n = idx >> 9, k = idx & 511;
      float x = Uh[(size_t)k * H_ + n];
      __nv_bfloat16 hi = __float2bfloat16(x);
      g_Uth[idx] = hi;
      g_Utl[idx] = __float2bfloat16(x - __bfloat162float(hi));
      float y = Wo[(size_t)k * D_ + n];
      __nv_bfloat16 hi2 = __float2bfloat16(y);
      g_Woth[idx] = hi2;
      g_Wotl[idx] = __float2bfloat16(y - __bfloat162float(hi2));
    }
  } else {
    int idx = (b - 3072) * 256 + threadIdx.x;
    if (idx < B_ * H_) {
      float z  = sigmoidf_(g_Gz[idx]);
      float hp = tanhf(g_Gh[idx]);
      float hn = fminf(fmaxf(z * hp, -5.f), 5.f);
      g_h[idx] = hn;
      __nv_bfloat16 hi = __float2bfloat16(hn);
      __nv_bfloat16 lo = __float2bfloat16(hn - __bfloat162float(hi));
      g_hh[idx] = hi;
      g_hl[idx] = lo;
      g_histh[idx] = hi;
      g_histl[idx] = lo;
    }
  }
}

__global__ void copy0_kernel(const float* __restrict__ inputs, float* __restrict__ out) {
  int idx = blockIdx.x * blockDim.x + threadIdx.x;
  if (idx >= B_ * D_) return;
  int b = idx / D_, d = idx % D_;
  out[(size_t)b * ((size_t)T_ * D_) + d] = inputs[idx];
}

// ---------------- launch ----------------
extern "C" void kernel_launch(void* const* d_in, const int* in_sizes, int n_in,
                              void* d_out, int out_size) {
  const float* inputs = (const float*)d_in[0];
  const float* Wz = (const float*)d_in[1];
  const float* Wr = (const float*)d_in[2];
  const float* Wh = (const float*)d_in[3];
  const float* Uz = (const float*)d_in[4];
  const float* Ur = (const float*)d_in[5];
  const float* Uh = (const float*)d_in[6];
  const float* bz = (const float*)d_in[7];
  const float* br = (const float*)d_in[8];
  const float* bh = (const float*)d_in[9];
  const float* Wo = (const float*)d_in[10];
  const float* bo = (const float*)d_in[11];
  float* out = (float*)d_out;

  cudaFuncSetAttribute(proj_kernel, cudaFuncAttributeMaxDynamicSharedMemorySize, 131072);
  cudaFuncSetAttribute(recur_kernel, cudaFuncAttributeMaxDynamicSharedMemorySize, RSMEM);

  // slot 0: pack + barrier reset
  pack_kernel<<<(D_ * NG_ + 255) / 256, 256>>>(Wr, Wz, Wh, br, bz, bh);
  // slot 1: fold + ccat + step1 (fused)
  setup1_kernel<<<640, 256>>>(Wo, Ur, Uz, inputs, bo);
  // slot 2: permuted bf16 splits + combine1 (fused)
  setup2_kernel<<<3328, 256>>>(Uh, Wo);
  // slot 3 (ncu-profiled slot): persistent recurrence (direct-poll barrier)
  recur_kernel<<<NCTA, 256, RSMEM>>>();
  // slot 4: t=0 output copy
  copy0_kernel<<<(B_ * D_ + 255) / 256, 256>>>(inputs, out);
  // slot 5: deferred projection
  proj_kernel<<<dim3(4, T_ - 1), 256, 131072>>>(out, bo);
}